// round 1
// baseline (speedup 1.0000x reference)
#include <cuda_runtime.h>

#define N_NODES 16384
#define IN_DIM 256
#define HID 128
#define MAXL 128
#define NCLS 64
#define KW 3
#define EPS 1e-5f
#define PAD 4
#define XS (MAXL + 2*PAD)   // 136 floats per row, 4 zero columns each side

// -------- device scratch (no allocations allowed) --------
__device__ float g_H[N_NODES * HID];                // local-encoder output
__device__ float g_pooled[N_NODES * HID];           // pooled per-node vector
__device__ float g_convT[3 * KW * HID * HID];       // conv weights [layer][tap][ci][o]

__device__ __forceinline__ float gelu_exact(float x) {
    return 0.5f * x * (1.0f + erff(x * 0.7071067811865476f));
}

// ------------------------------------------------------------------
// Transpose conv weights once: convT[((i*KW+kk)*HID+ci)*HID+o] =
//   conv_w[((i*HID+o)*HID+ci)*KW+kk]   (so per-tap smem loads are coalesced)
// ------------------------------------------------------------------
__global__ void k_transpose_conv(const float* __restrict__ conv_w) {
    int e = blockIdx.x * blockDim.x + threadIdx.x;
    if (e >= 3 * KW * HID * HID) return;
    int o  = e & (HID - 1);
    int t  = e >> 7;
    int ci = t & (HID - 1);
    t >>= 7;
    int kk = t % KW;
    int i  = t / KW;
    g_convT[e] = conv_w[((i * HID + o) * HID + ci) * KW + kk];
}

// ------------------------------------------------------------------
// Local encoder: H = LN(GELU(X @ W + b)).  One block per node.
// ------------------------------------------------------------------
__global__ __launch_bounds__(128) void k_local(
    const float* __restrict__ feat, const float* __restrict__ W,
    const float* __restrict__ b, const float* __restrict__ lnw,
    const float* __restrict__ lnb)
{
    __shared__ float xs[IN_DIM];
    __shared__ float red[8];
    int n = blockIdx.x;
    int c = threadIdx.x;
    xs[c]       = feat[n * IN_DIM + c];
    xs[c + 128] = feat[n * IN_DIM + c + 128];
    __syncthreads();

    float acc = b[c];
    #pragma unroll 8
    for (int i = 0; i < IN_DIM; ++i)
        acc += xs[i] * W[i * HID + c];
    float v = gelu_exact(acc);

    float s = v, s2 = v * v;
    #pragma unroll
    for (int off = 16; off; off >>= 1) {
        s  += __shfl_xor_sync(0xffffffffu, s,  off);
        s2 += __shfl_xor_sync(0xffffffffu, s2, off);
    }
    int warp = c >> 5, lane = c & 31;
    if (lane == 0) { red[warp] = s; red[4 + warp] = s2; }
    __syncthreads();
    s  = red[0] + red[1] + red[2] + red[3];
    s2 = red[4] + red[5] + red[6] + red[7];
    float m   = s * (1.0f / HID);
    float var = s2 * (1.0f / HID) - m * m;
    float inv = rsqrtf(var + EPS);
    g_H[n * HID + c] = (v - m) * inv * lnw[c] + lnb[c];
}

// ------------------------------------------------------------------
// 128x128x128 GEMM microkernel: C[m][n] += sum_k Wt[k][m] * B[k][n+SHIFT]
// Wt: smem [128][128] (K-major).  B: smem [128][XS] with zero pads so
// SHIFT in {-4..4} never needs predicates.
// ------------------------------------------------------------------
template<int SHIFT>
__device__ __forceinline__ void gemm_tap(float C[8][8], const float* __restrict__ Wt,
                                         const float* __restrict__ B, int m0, int n0)
{
    const float* brow = B + PAD + n0 + SHIFT;
    const float* wrow = Wt + m0;
    #pragma unroll 2
    for (int k = 0; k < HID; ++k) {
        float a[8], bb[8];
        float4 a0 = *(const float4*)(wrow);
        float4 a1 = *(const float4*)(wrow + 4);
        a[0]=a0.x; a[1]=a0.y; a[2]=a0.z; a[3]=a0.w;
        a[4]=a1.x; a[5]=a1.y; a[6]=a1.z; a[7]=a1.w;
        if ((SHIFT & 3) == 0) {  // 16B-aligned shifts -> vector loads
            float4 b0 = *(const float4*)(brow);
            float4 b1 = *(const float4*)(brow + 4);
            bb[0]=b0.x; bb[1]=b0.y; bb[2]=b0.z; bb[3]=b0.w;
            bb[4]=b1.x; bb[5]=b1.y; bb[6]=b1.z; bb[7]=b1.w;
        } else {
            #pragma unroll
            for (int j = 0; j < 8; ++j) bb[j] = brow[j];
        }
        #pragma unroll
        for (int i = 0; i < 8; ++i)
            #pragma unroll
            for (int j = 0; j < 8; ++j)
                C[i][j] += a[i] * bb[j];
        wrow += HID;
        brow += XS;
    }
}

// ------------------------------------------------------------------
// Main per-node pipeline: gather -> ssm_in GEMM -> 3 dilated conv layers
// (3 shifted GEMM taps each) + GELU + LN(over L) -> masked pool -> out_W matvec.
// One block (256 threads) per node, everything smem-resident.
// ------------------------------------------------------------------
__global__ __launch_bounds__(256, 1) void k_main(
    const int* __restrict__ nidx, const int* __restrict__ nlen,
    const float* __restrict__ ssmW, const float* __restrict__ ssmB,
    const float* __restrict__ convB, const float* __restrict__ lnW,
    const float* __restrict__ lnB, const float* __restrict__ outW,
    const float* __restrict__ outB)
{
    extern __shared__ float smf[];
    float* Xa   = smf;                       // [HID][XS]
    float* Xb   = smf + HID * XS;            // [HID][XS]
    float* Wt   = smf + 2 * HID * XS;        // [HID][HID]
    float* svec = Wt + HID * HID;            // [HID]

    const int n   = blockIdx.x;
    const int tid = threadIdx.x;
    const int tx = tid & 15, ty = tid >> 4;
    const int m0 = ty * 8, n0 = tx * 8;
    const int len = nlen[n];

    // zero the pad columns of both buffers (only written once)
    for (int e = tid; e < HID * 8; e += 256) {
        int r = e >> 3, p = e & 7;
        int col = (p < PAD) ? p : (XS - 8 + p);
        Xa[r * XS + col] = 0.f;
        Xb[r * XS + col] = 0.f;
    }

    // gather masked neighbor features transposed: Xa[k][l] = H[idx[l]][k] * mask
    const int* idxrow = nidx + n * MAXL;
    for (int e = tid; e < MAXL * HID; e += 256) {
        int l = e >> 7, k = e & (HID - 1);
        float v = 0.f;
        if (l < len) v = g_H[idxrow[l] * HID + k];
        Xa[k * XS + PAD + l] = v;
    }
    // ssm_in weight is already [k][c] = [K][M] layout
    for (int e = tid; e < HID * HID; e += 256) Wt[e] = ssmW[e];
    __syncthreads();

    float C[8][8];
    #pragma unroll
    for (int i = 0; i < 8; ++i)
        #pragma unroll
        for (int j = 0; j < 8; ++j) C[i][j] = 0.f;

    gemm_tap<0>(C, Wt, Xa, m0, n0);   // X0[c][l] = sum_k W[k][c] * seqT[k][l]

    #pragma unroll
    for (int i = 0; i < 8; ++i) {
        float bv = ssmB[m0 + i];
        #pragma unroll
        for (int j = 0; j < 8; ++j)
            Xb[(m0 + i) * XS + PAD + n0 + j] = C[i][j] + bv;
    }
    __syncthreads();

    float* src = Xb;
    float* dst = Xa;

    for (int layer = 0; layer < 3; ++layer) {
        const int d = 1 << layer;
        #pragma unroll
        for (int i = 0; i < 8; ++i)
            #pragma unroll
            for (int j = 0; j < 8; ++j) C[i][j] = 0.f;

        for (int kk = 0; kk < KW; ++kk) {
            const float* wsrc = g_convT + (layer * KW + kk) * HID * HID;
            for (int e = tid; e < HID * HID; e += 256) Wt[e] = wsrc[e];
            __syncthreads();
            int shift = (kk - 1) * d;
            switch (shift) {
                case -4: gemm_tap<-4>(C, Wt, src, m0, n0); break;
                case -2: gemm_tap<-2>(C, Wt, src, m0, n0); break;
                case -1: gemm_tap<-1>(C, Wt, src, m0, n0); break;
                case  0: gemm_tap< 0>(C, Wt, src, m0, n0); break;
                case  1: gemm_tap< 1>(C, Wt, src, m0, n0); break;
                case  2: gemm_tap< 2>(C, Wt, src, m0, n0); break;
                default: gemm_tap< 4>(C, Wt, src, m0, n0); break;
            }
            __syncthreads();
        }

        // epilogue: +bias(row) -> GELU -> LN over L (per row), ln weights indexed by l
        float rs[8], rq[8];
        #pragma unroll
        for (int i = 0; i < 8; ++i) {
            float bv = convB[layer * HID + m0 + i];
            rs[i] = 0.f; rq[i] = 0.f;
            #pragma unroll
            for (int j = 0; j < 8; ++j) {
                float z = gelu_exact(C[i][j] + bv);
                C[i][j] = z;
                rs[i] += z;
                rq[i] += z * z;
            }
        }
        #pragma unroll
        for (int i = 0; i < 8; ++i) {
            #pragma unroll
            for (int off = 8; off; off >>= 1) {   // reduce across the 16 tx lanes
                rs[i] += __shfl_xor_sync(0xffffffffu, rs[i], off);
                rq[i] += __shfl_xor_sync(0xffffffffu, rq[i], off);
            }
        }

        float lw[8], lb[8];
        #pragma unroll
        for (int j = 0; j < 8; ++j) {
            lw[j] = lnW[layer * HID + n0 + j];
            lb[j] = lnB[layer * HID + n0 + j];
        }

        if (layer < 2) {
            #pragma unroll
            for (int i = 0; i < 8; ++i) {
                float m   = rs[i] * (1.f / MAXL);
                float inv = rsqrtf(rq[i] * (1.f / MAXL) - m * m + EPS);
                #pragma unroll
                for (int j = 0; j < 8; ++j)
                    dst[(m0 + i) * XS + PAD + n0 + j] = (C[i][j] - m) * inv * lw[j] + lb[j];
            }
            float* t = src; src = dst; dst = t;
            __syncthreads();
        } else {
            // final layer: fuse masked pooling, skip writing the full tile
            float ms[8];
            #pragma unroll
            for (int i = 0; i < 8; ++i) {
                float m   = rs[i] * (1.f / MAXL);
                float inv = rsqrtf(rq[i] * (1.f / MAXL) - m * m + EPS);
                ms[i] = 0.f;
                #pragma unroll
                for (int j = 0; j < 8; ++j) {
                    float o = (C[i][j] - m) * inv * lw[j] + lb[j];
                    if (n0 + j < len) ms[i] += o;
                }
            }
            #pragma unroll
            for (int i = 0; i < 8; ++i) {
                #pragma unroll
                for (int off = 8; off; off >>= 1)
                    ms[i] += __shfl_xor_sync(0xffffffffu, ms[i], off);
            }
            if (tx == 0) {
                #pragma unroll
                for (int i = 0; i < 8; ++i) svec[m0 + i] = ms[i];
            }
        }
    }
    __syncthreads();

    // pooled = (svec @ outW + cnt*outB) / max(cnt,1)   (mask/pool commuted past out_W)
    if (tid < HID) {
        float acc = 0.f;
        #pragma unroll 8
        for (int c = 0; c < HID; ++c)
            acc += svec[c] * outW[c * HID + tid];
        float cnt   = (float)len;
        float denom = fmaxf(cnt, 1.f);
        g_pooled[n * HID + tid] = (acc + cnt * outB[tid]) / denom;
    }
}

// ------------------------------------------------------------------
// Classifier head: logits = GELU(pooled @ W1 + b1) @ W2 + b2
// ------------------------------------------------------------------
__global__ __launch_bounds__(64) void k_cls(
    const float* __restrict__ W1, const float* __restrict__ b1,
    const float* __restrict__ W2, const float* __restrict__ b2,
    float* __restrict__ out)
{
    __shared__ float p[HID];
    __shared__ float g[64];
    int n = blockIdx.x;
    int j = threadIdx.x;
    p[j]      = g_pooled[n * HID + j];
    p[j + 64] = g_pooled[n * HID + j + 64];
    __syncthreads();
    float acc = b1[j];
    #pragma unroll 8
    for (int c = 0; c < HID; ++c)
        acc += p[c] * W1[c * 64 + j];
    g[j] = gelu_exact(acc);
    __syncthreads();
    float acc2 = b2[j];
    #pragma unroll 8
    for (int t = 0; t < 64; ++t)
        acc2 += g[t] * W2[t * 64 + j];
    out[n * NCLS + j] = acc2;
}

// ------------------------------------------------------------------
extern "C" void kernel_launch(void* const* d_in, const int* in_sizes, int n_in,
                              void* d_out, int out_size)
{
    (void)in_sizes; (void)n_in; (void)out_size;
    const float* node_feat  = (const float*)d_in[0];
    const int*   nidx       = (const int*)  d_in[1];
    const int*   nlen       = (const int*)  d_in[2];
    const float* local_W    = (const float*)d_in[3];
    const float* local_b    = (const float*)d_in[4];
    const float* local_ln_w = (const float*)d_in[5];
    const float* local_ln_b = (const float*)d_in[6];
    const float* ssm_in_W   = (const float*)d_in[7];
    const float* ssm_in_b   = (const float*)d_in[8];
    const float* conv_w     = (const float*)d_in[9];
    const float* conv_b     = (const float*)d_in[10];
    const float* ln_w       = (const float*)d_in[11];
    const float* ln_b       = (const float*)d_in[12];
    const float* out_W      = (const float*)d_in[13];
    const float* out_b      = (const float*)d_in[14];
    const float* cls_W1     = (const float*)d_in[15];
    const float* cls_b1     = (const float*)d_in[16];
    const float* cls_W2     = (const float*)d_in[17];
    const float* cls_b2     = (const float*)d_in[18];
    float* out = (float*)d_out;

    size_t smem_bytes = (size_t)(2 * HID * XS + HID * HID + HID) * sizeof(float);
    cudaFuncSetAttribute(k_main, cudaFuncAttributeMaxDynamicSharedMemorySize,
                         (int)smem_bytes);

    k_transpose_conv<<<(3 * KW * HID * HID + 255) / 256, 256>>>(conv_w);
    k_local<<<N_NODES, 128>>>(node_feat, local_W, local_b, local_ln_w, local_ln_b);
    k_main<<<N_NODES, 256, smem_bytes>>>(nidx, nlen, ssm_in_W, ssm_in_b,
                                         conv_b, ln_w, ln_b, out_W, out_b);
    k_cls<<<N_NODES, 64>>>(cls_W1, cls_b1, cls_W2, cls_b2, out);
}

// round 2
// speedup vs baseline: 1.0014x; 1.0014x over previous
#include <cuda_runtime.h>

#define N_NODES 16384
#define IN_DIM 256
#define HID 128
#define MAXL 128
#define NCLS 64
#define KW 3
#define EPS 1e-5f
#define PAD 4
#define XS (MAXL + 2*PAD)   // 136 floats per row, 4 zero columns each side

// -------- device scratch (no allocations allowed) --------
__device__ float g_H[N_NODES * HID];                // local-encoder output
__device__ float g_pooled[N_NODES * HID];           // pooled per-node vector
__device__ float g_convT[3 * KW * HID * HID];       // conv weights [layer][tap][ci][o]

__device__ __forceinline__ float gelu_exact(float x) {
    return 0.5f * x * (1.0f + erff(x * 0.7071067811865476f));
}

// ------------------------------------------------------------------
// Transpose conv weights once: convT[((i*KW+kk)*HID+ci)*HID+o] =
//   conv_w[((i*HID+o)*HID+ci)*KW+kk]   (so per-tap smem loads are coalesced)
// ------------------------------------------------------------------
__global__ void k_transpose_conv(const float* __restrict__ conv_w) {
    int e = blockIdx.x * blockDim.x + threadIdx.x;
    if (e >= 3 * KW * HID * HID) return;
    int o  = e & (HID - 1);
    int t  = e >> 7;
    int ci = t & (HID - 1);
    t >>= 7;
    int kk = t % KW;
    int i  = t / KW;
    g_convT[e] = conv_w[((i * HID + o) * HID + ci) * KW + kk];
}

// ------------------------------------------------------------------
// Local encoder: H = LN(GELU(X @ W + b)).  One block per node.
// ------------------------------------------------------------------
__global__ __launch_bounds__(128) void k_local(
    const float* __restrict__ feat, const float* __restrict__ W,
    const float* __restrict__ b, const float* __restrict__ lnw,
    const float* __restrict__ lnb)
{
    __shared__ float xs[IN_DIM];
    __shared__ float red[8];
    int n = blockIdx.x;
    int c = threadIdx.x;
    xs[c]       = feat[n * IN_DIM + c];
    xs[c + 128] = feat[n * IN_DIM + c + 128];
    __syncthreads();

    float acc = b[c];
    #pragma unroll 8
    for (int i = 0; i < IN_DIM; ++i)
        acc += xs[i] * W[i * HID + c];
    float v = gelu_exact(acc);

    float s = v, s2 = v * v;
    #pragma unroll
    for (int off = 16; off; off >>= 1) {
        s  += __shfl_xor_sync(0xffffffffu, s,  off);
        s2 += __shfl_xor_sync(0xffffffffu, s2, off);
    }
    int warp = c >> 5, lane = c & 31;
    if (lane == 0) { red[warp] = s; red[4 + warp] = s2; }
    __syncthreads();
    s  = red[0] + red[1] + red[2] + red[3];
    s2 = red[4] + red[5] + red[6] + red[7];
    float m   = s * (1.0f / HID);
    float var = s2 * (1.0f / HID) - m * m;
    float inv = rsqrtf(var + EPS);
    g_H[n * HID + c] = (v - m) * inv * lnw[c] + lnb[c];
}

// ------------------------------------------------------------------
// 128x128x128 GEMM microkernel: C[m][n] += sum_k Wt[k][m] * B[k][n+SHIFT]
// Wt: smem [128][128] (K-major).  B: smem [128][XS] with zero pads so
// SHIFT in {-4..4} never needs predicates.
// ------------------------------------------------------------------
template<int SHIFT>
__device__ __forceinline__ void gemm_tap(float C[8][8], const float* __restrict__ Wt,
                                         const float* __restrict__ B, int m0, int n0)
{
    const float* brow = B + PAD + n0 + SHIFT;
    const float* wrow = Wt + m0;
    #pragma unroll 2
    for (int k = 0; k < HID; ++k) {
        float a[8], bb[8];
        float4 a0 = *(const float4*)(wrow);
        float4 a1 = *(const float4*)(wrow + 4);
        a[0]=a0.x; a[1]=a0.y; a[2]=a0.z; a[3]=a0.w;
        a[4]=a1.x; a[5]=a1.y; a[6]=a1.z; a[7]=a1.w;
        if ((SHIFT & 3) == 0) {  // 16B-aligned shifts -> vector loads
            float4 b0 = *(const float4*)(brow);
            float4 b1 = *(const float4*)(brow + 4);
            bb[0]=b0.x; bb[1]=b0.y; bb[2]=b0.z; bb[3]=b0.w;
            bb[4]=b1.x; bb[5]=b1.y; bb[6]=b1.z; bb[7]=b1.w;
        } else {
            #pragma unroll
            for (int j = 0; j < 8; ++j) bb[j] = brow[j];
        }
        #pragma unroll
        for (int i = 0; i < 8; ++i)
            #pragma unroll
            for (int j = 0; j < 8; ++j)
                C[i][j] += a[i] * bb[j];
        wrow += HID;
        brow += XS;
    }
}

// ------------------------------------------------------------------
// Main per-node pipeline: gather -> ssm_in GEMM -> 3 dilated conv layers
// (3 shifted GEMM taps each) + GELU + LN(over L) -> masked pool -> out_W matvec.
// One block (256 threads) per node, everything smem-resident.
// ------------------------------------------------------------------
__global__ __launch_bounds__(256, 1) void k_main(
    const int* __restrict__ nidx, const int* __restrict__ nlen,
    const float* __restrict__ ssmW, const float* __restrict__ ssmB,
    const float* __restrict__ convB, const float* __restrict__ lnW,
    const float* __restrict__ lnB, const float* __restrict__ outW,
    const float* __restrict__ outB)
{
    extern __shared__ float smf[];
    float* Xa   = smf;                       // [HID][XS]
    float* Xb   = smf + HID * XS;            // [HID][XS]
    float* Wt   = smf + 2 * HID * XS;        // [HID][HID]
    float* svec = Wt + HID * HID;            // [HID]

    const int n   = blockIdx.x;
    const int tid = threadIdx.x;
    const int tx = tid & 15, ty = tid >> 4;
    const int m0 = ty * 8, n0 = tx * 8;
    const int len = nlen[n];

    // zero the pad columns of both buffers (only written once)
    for (int e = tid; e < HID * 8; e += 256) {
        int r = e >> 3, p = e & 7;
        int col = (p < PAD) ? p : (XS - 8 + p);
        Xa[r * XS + col] = 0.f;
        Xb[r * XS + col] = 0.f;
    }

    // gather masked neighbor features transposed: Xa[k][l] = H[idx[l]][k] * mask
    const int* idxrow = nidx + n * MAXL;
    for (int e = tid; e < MAXL * HID; e += 256) {
        int l = e >> 7, k = e & (HID - 1);
        float v = 0.f;
        if (l < len) v = g_H[idxrow[l] * HID + k];
        Xa[k * XS + PAD + l] = v;
    }
    // ssm_in weight is already [k][c] = [K][M] layout
    for (int e = tid; e < HID * HID; e += 256) Wt[e] = ssmW[e];
    __syncthreads();

    float C[8][8];
    #pragma unroll
    for (int i = 0; i < 8; ++i)
        #pragma unroll
        for (int j = 0; j < 8; ++j) C[i][j] = 0.f;

    gemm_tap<0>(C, Wt, Xa, m0, n0);   // X0[c][l] = sum_k W[k][c] * seqT[k][l]

    #pragma unroll
    for (int i = 0; i < 8; ++i) {
        float bv = ssmB[m0 + i];
        #pragma unroll
        for (int j = 0; j < 8; ++j)
            Xb[(m0 + i) * XS + PAD + n0 + j] = C[i][j] + bv;
    }
    __syncthreads();

    float* src = Xb;
    float* dst = Xa;

    for (int layer = 0; layer < 3; ++layer) {
        const int d = 1 << layer;
        #pragma unroll
        for (int i = 0; i < 8; ++i)
            #pragma unroll
            for (int j = 0; j < 8; ++j) C[i][j] = 0.f;

        for (int kk = 0; kk < KW; ++kk) {
            const float* wsrc = g_convT + (layer * KW + kk) * HID * HID;
            for (int e = tid; e < HID * HID; e += 256) Wt[e] = wsrc[e];
            __syncthreads();
            int shift = (kk - 1) * d;
            switch (shift) {
                case -4: gemm_tap<-4>(C, Wt, src, m0, n0); break;
                case -2: gemm_tap<-2>(C, Wt, src, m0, n0); break;
                case -1: gemm_tap<-1>(C, Wt, src, m0, n0); break;
                case  0: gemm_tap< 0>(C, Wt, src, m0, n0); break;
                case  1: gemm_tap< 1>(C, Wt, src, m0, n0); break;
                case  2: gemm_tap< 2>(C, Wt, src, m0, n0); break;
                default: gemm_tap< 4>(C, Wt, src, m0, n0); break;
            }
            __syncthreads();
        }

        // epilogue: +bias(row) -> GELU -> LN over L (per row), ln weights indexed by l
        float rs[8], rq[8];
        #pragma unroll
        for (int i = 0; i < 8; ++i) {
            float bv = convB[layer * HID + m0 + i];
            rs[i] = 0.f; rq[i] = 0.f;
            #pragma unroll
            for (int j = 0; j < 8; ++j) {
                float z = gelu_exact(C[i][j] + bv);
                C[i][j] = z;
                rs[i] += z;
                rq[i] += z * z;
            }
        }
        #pragma unroll
        for (int i = 0; i < 8; ++i) {
            #pragma unroll
            for (int off = 8; off; off >>= 1) {   // reduce across the 16 tx lanes
                rs[i] += __shfl_xor_sync(0xffffffffu, rs[i], off);
                rq[i] += __shfl_xor_sync(0xffffffffu, rq[i], off);
            }
        }

        float lw[8], lb[8];
        #pragma unroll
        for (int j = 0; j < 8; ++j) {
            lw[j] = lnW[layer * HID + n0 + j];
            lb[j] = lnB[layer * HID + n0 + j];
        }

        if (layer < 2) {
            #pragma unroll
            for (int i = 0; i < 8; ++i) {
                float m   = rs[i] * (1.f / MAXL);
                float inv = rsqrtf(rq[i] * (1.f / MAXL) - m * m + EPS);
                #pragma unroll
                for (int j = 0; j < 8; ++j)
                    dst[(m0 + i) * XS + PAD + n0 + j] = (C[i][j] - m) * inv * lw[j] + lb[j];
            }
            float* t = src; src = dst; dst = t;
            __syncthreads();
        } else {
            // final layer: fuse masked pooling, skip writing the full tile
            float ms[8];
            #pragma unroll
            for (int i = 0; i < 8; ++i) {
                float m   = rs[i] * (1.f / MAXL);
                float inv = rsqrtf(rq[i] * (1.f / MAXL) - m * m + EPS);
                ms[i] = 0.f;
                #pragma unroll
                for (int j = 0; j < 8; ++j) {
                    float o = (C[i][j] - m) * inv * lw[j] + lb[j];
                    if (n0 + j < len) ms[i] += o;
                }
            }
            #pragma unroll
            for (int i = 0; i < 8; ++i) {
                #pragma unroll
                for (int off = 8; off; off >>= 1)
                    ms[i] += __shfl_xor_sync(0xffffffffu, ms[i], off);
            }
            if (tx == 0) {
                #pragma unroll
                for (int i = 0; i < 8; ++i) svec[m0 + i] = ms[i];
            }
        }
    }
    __syncthreads();

    // pooled = (svec @ outW + cnt*outB) / max(cnt,1)   (mask/pool commuted past out_W)
    if (tid < HID) {
        float acc = 0.f;
        #pragma unroll 8
        for (int c = 0; c < HID; ++c)
            acc += svec[c] * outW[c * HID + tid];
        float cnt   = (float)len;
        float denom = fmaxf(cnt, 1.f);
        g_pooled[n * HID + tid] = (acc + cnt * outB[tid]) / denom;
    }
}

// ------------------------------------------------------------------
// Classifier head: logits = GELU(pooled @ W1 + b1) @ W2 + b2
// ------------------------------------------------------------------
__global__ __launch_bounds__(64) void k_cls(
    const float* __restrict__ W1, const float* __restrict__ b1,
    const float* __restrict__ W2, const float* __restrict__ b2,
    float* __restrict__ out)
{
    __shared__ float p[HID];
    __shared__ float g[64];
    int n = blockIdx.x;
    int j = threadIdx.x;
    p[j]      = g_pooled[n * HID + j];
    p[j + 64] = g_pooled[n * HID + j + 64];
    __syncthreads();
    float acc = b1[j];
    #pragma unroll 8
    for (int c = 0; c < HID; ++c)
        acc += p[c] * W1[c * 64 + j];
    g[j] = gelu_exact(acc);
    __syncthreads();
    float acc2 = b2[j];
    #pragma unroll 8
    for (int t = 0; t < 64; ++t)
        acc2 += g[t] * W2[t * 64 + j];
    out[n * NCLS + j] = acc2;
}

// ------------------------------------------------------------------
extern "C" void kernel_launch(void* const* d_in, const int* in_sizes, int n_in,
                              void* d_out, int out_size)
{
    (void)in_sizes; (void)n_in; (void)out_size;
    const float* node_feat  = (const float*)d_in[0];
    const int*   nidx       = (const int*)  d_in[1];
    const int*   nlen       = (const int*)  d_in[2];
    const float* local_W    = (const float*)d_in[3];
    const float* local_b    = (const float*)d_in[4];
    const float* local_ln_w = (const float*)d_in[5];
    const float* local_ln_b = (const float*)d_in[6];
    const float* ssm_in_W   = (const float*)d_in[7];
    const float* ssm_in_b   = (const float*)d_in[8];
    const float* conv_w     = (const float*)d_in[9];
    const float* conv_b     = (const float*)d_in[10];
    const float* ln_w       = (const float*)d_in[11];
    const float* ln_b       = (const float*)d_in[12];
    const float* out_W      = (const float*)d_in[13];
    const float* out_b      = (const float*)d_in[14];
    const float* cls_W1     = (const float*)d_in[15];
    const float* cls_b1     = (const float*)d_in[16];
    const float* cls_W2     = (const float*)d_in[17];
    const float* cls_b2     = (const float*)d_in[18];
    float* out = (float*)d_out;

    size_t smem_bytes = (size_t)(2 * HID * XS + HID * HID + HID) * sizeof(float);
    cudaFuncSetAttribute(k_main, cudaFuncAttributeMaxDynamicSharedMemorySize,
                         (int)smem_bytes);

    k_transpose_conv<<<(3 * KW * HID * HID + 255) / 256, 256>>>(conv_w);
    k_local<<<N_NODES, 128>>>(node_feat, local_W, local_b, local_ln_w, local_ln_b);
    k_main<<<N_NODES, 256, smem_bytes>>>(nidx, nlen, ssm_in_W, ssm_in_b,
                                         conv_b, ln_w, ln_b, out_W, out_b);
    k_cls<<<N_NODES, 64>>>(cls_W1, cls_b1, cls_W2, cls_b2, out);
}

// round 4
// speedup vs baseline: 5.8008x; 5.7928x over previous
#include <cuda_runtime.h>
#include <cstdint>

#if defined(__CUDA_ARCH_FEAT_SM103_ALL) || \
    (defined(__CUDA_ARCH_SPECIFIC__) && (__CUDA_ARCH_SPECIFIC__ == 1030)) || \
    (defined(__CUDA_ARCH_FAMILY_SPECIFIC__) && (__CUDA_ARCH_FAMILY_SPECIFIC__ == 1030))
#define TC_PATH 1
#else
#define TC_PATH 0
#endif

#define N_NODES 16384
#define IN_DIM 256
#define HID 128
#define MAXL 128
#define NCLS 64
#define EPS 1e-5f
#define D0 8
#define SA 144
#define SB 276
#define PAD 4
#define XS (MAXL + 2*PAD)

// ---------------- device scratch (no allocations allowed) ----------------
__device__ float g_H[N_NODES * HID];
__device__ float g_pooled[N_NODES * HID];
__device__ float g_Wswz[10 * HID * HID];    // swizzled tf32 tiles (tensor path)
__device__ float g_Wplain[10 * HID * HID];  // plain [k][m] fp32 tiles (fallback path)

// idesc kind::tf32: dtype F32(1<<4), atype TF32(2<<7), btype TF32(2<<10), N=128(16<<17), M=128(8<<24)
static constexpr uint32_t IDESC =
    (1u << 4) | (2u << 7) | (2u << 10) | (16u << 17) | (8u << 24);
// SW128 K-major smem descriptor: layout=2, version=1, SBO=64 (1024B), LBO=1 (16B)
static constexpr uint64_t DESC_BASE =
    (uint64_t(2) << 61) | (uint64_t(1) << 46) | (uint64_t(64) << 32) | (uint64_t(1) << 16);

__device__ __forceinline__ float gelu_exact(float x) {
    return 0.5f * x * (1.0f + erff(x * 0.7071067811865476f));
}
__device__ __forceinline__ float tf32r(float x) {
    uint32_t u;
    asm("cvt.rna.tf32.f32 %0, %1;" : "=r"(u) : "f"(x));
    return __uint_as_float(u);
}
__device__ __forceinline__ uint32_t smem_u32(const void* p) {
    uint32_t a;
    asm("{ .reg .u64 t; cvta.to.shared.u64 t, %1; cvt.u32.u64 %0, t; }" : "=r"(a) : "l"(p));
    return a;
}
// byte offset of (row, col) in a [128 x 128 fp32] K-major SW128 blocked tile
__device__ __forceinline__ uint32_t swz_off(int row, int col) {
    uint32_t off = ((uint32_t)(row >> 3) + (uint32_t)(col >> 5) * 16u) * 1024u
                 + (uint32_t)(row & 7) * 128u + (uint32_t)(col & 31) * 4u;
    return off ^ ((off >> 3) & 0x70u);
}

// ------------------------------------------------------------------
// Prep: build both weight forms.
// tile 0: A[c][k] = ssm_in_W[k][c]; tiles 1..9: A[co][ci] = conv_w[layer][co][ci][kk]
// ------------------------------------------------------------------
__global__ void k_prep(const float* __restrict__ ssmW, const float* __restrict__ convW) {
    int e = blockIdx.x * blockDim.x + threadIdx.x;
    if (e >= 10 * HID * HID) return;
    int tile = e >> 14;
    int r = (e >> 7) & 127;   // M index (output channel)
    int k = e & 127;          // K index (input channel)
    float v;
    if (tile == 0) {
        v = ssmW[k * HID + r];
    } else {
        int t = tile - 1, layer = t / 3, kk = t % 3;
        v = convW[((layer * HID + r) * HID + k) * 3 + kk];
    }
    g_Wplain[tile * (HID * HID) + k * HID + r] = v;
    *(float*)((char*)(g_Wswz + tile * (HID * HID)) + swz_off(r, k)) = tf32r(v);
}

// ------------------------------------------------------------------
// Local encoder, 8 nodes per block
// ------------------------------------------------------------------
__global__ __launch_bounds__(128) void k_local8(
    const float* __restrict__ feat, const float* __restrict__ W,
    const float* __restrict__ b, const float* __restrict__ lnw,
    const float* __restrict__ lnb)
{
    __shared__ float xs[8 * IN_DIM];
    __shared__ float reds[32], redq[32];
    int base = blockIdx.x * 8;
    int c = threadIdx.x;
    for (int e = c; e < 8 * IN_DIM; e += 128)
        xs[e] = feat[base * IN_DIM + e];
    __syncthreads();

    float acc[8];
    float bb = b[c];
    #pragma unroll
    for (int nb = 0; nb < 8; ++nb) acc[nb] = bb;
    for (int i = 0; i < IN_DIM; ++i) {
        float wv = W[i * HID + c];
        #pragma unroll
        for (int nb = 0; nb < 8; ++nb) acc[nb] += xs[nb * IN_DIM + i] * wv;
    }
    int warp = c >> 5, lane = c & 31;
    float v[8];
    #pragma unroll
    for (int nb = 0; nb < 8; ++nb) {
        v[nb] = gelu_exact(acc[nb]);
        float s = v[nb], q = v[nb] * v[nb];
        #pragma unroll
        for (int off = 16; off; off >>= 1) {
            s += __shfl_xor_sync(0xffffffffu, s, off);
            q += __shfl_xor_sync(0xffffffffu, q, off);
        }
        if (lane == 0) { reds[warp * 8 + nb] = s; redq[warp * 8 + nb] = q; }
    }
    __syncthreads();
    #pragma unroll
    for (int nb = 0; nb < 8; ++nb) {
        float s = reds[nb] + reds[8 + nb] + reds[16 + nb] + reds[24 + nb];
        float q = redq[nb] + redq[8 + nb] + redq[16 + nb] + redq[24 + nb];
        float m = s * (1.f / HID);
        float inv = rsqrtf(q * (1.f / HID) - m * m + EPS);
        g_H[(base + nb) * HID + c] = (v[nb] - m) * inv * lnw[c] + lnb[c];
    }
}

// ================= tensor-path helpers (guarded) =================
#if TC_PATH
#define MBAR_INIT(a, cnt) \
    asm volatile("mbarrier.init.shared.b64 [%0], %1;" :: "r"(a), "r"((uint32_t)(cnt)) : "memory")
#define MBAR_EXPECT(a, bytes) \
    asm volatile("mbarrier.arrive.expect_tx.shared.b64 _, [%0], %1;" :: "r"(a), "r"((uint32_t)(bytes)) : "memory")

__device__ __forceinline__ void mbar_wait(uint32_t mbar, int parity) {
    asm volatile(
        "{\n\t.reg .pred P1;\n\t"
        "WL_%=:\n\t"
        "mbarrier.try_wait.parity.acquire.cta.shared::cta.b64 P1, [%0], %1, 0x989680;\n\t"
        "@P1 bra.uni WD_%=;\n\t"
        "bra.uni WL_%=;\n\t"
        "WD_%=:\n\t}"
        :: "r"(mbar), "r"((uint32_t)parity) : "memory");
}
__device__ __forceinline__ void bulk_g2s(uint32_t dst, const void* src, uint32_t bytes, uint32_t mbar) {
    asm volatile(
        "cp.async.bulk.shared::cluster.global.mbarrier::complete_tx::bytes [%0], [%1], %2, [%3];"
        :: "r"(dst), "l"(src), "r"(bytes), "r"(mbar) : "memory");
}

#define TC_ALLOC(sa, n) \
    asm volatile("tcgen05.alloc.cta_group::1.sync.aligned.shared::cta.b32 [%0], %1;" :: "r"(sa), "r"((uint32_t)(n)) : "memory")
#define TC_RELINQ() \
    asm volatile("tcgen05.relinquish_alloc_permit.cta_group::1.sync.aligned;")
#define TC_DEALLOC(t, n) \
    asm volatile("tcgen05.dealloc.cta_group::1.sync.aligned.b32 %0, %1;" :: "r"(t), "r"((uint32_t)(n)))
#define TC_COMMIT(mb) \
    asm volatile("tcgen05.commit.cta_group::1.mbarrier::arrive::one.shared::cluster.b64 [%0];" :: "r"(mb) : "memory")
#define TC_FENCE_BEFORE() asm volatile("tcgen05.fence::before_thread_sync;" ::: "memory")
#define TC_FENCE_AFTER()  asm volatile("tcgen05.fence::after_thread_sync;" ::: "memory")
#define TC_WAIT_LD() asm volatile("tcgen05.wait::ld.sync.aligned;" ::: "memory")
#define TC_WAIT_ST() asm volatile("tcgen05.wait::st.sync.aligned;" ::: "memory")
#define FENCE_PROXY() asm volatile("fence.proxy.async.shared::cta;" ::: "memory")

#define TCLD32(r, adr) \
    asm volatile( \
        "tcgen05.ld.sync.aligned.32x32b.x32.b32 " \
        "{%0, %1, %2, %3, %4, %5, %6, %7, %8, %9, %10, %11, %12, %13, %14, %15, " \
        " %16, %17, %18, %19, %20, %21, %22, %23, %24, %25, %26, %27, %28, %29, %30, %31}, [%32];" \
        : "=r"((r)[0]),  "=r"((r)[1]),  "=r"((r)[2]),  "=r"((r)[3]), \
          "=r"((r)[4]),  "=r"((r)[5]),  "=r"((r)[6]),  "=r"((r)[7]), \
          "=r"((r)[8]),  "=r"((r)[9]),  "=r"((r)[10]), "=r"((r)[11]), \
          "=r"((r)[12]), "=r"((r)[13]), "=r"((r)[14]), "=r"((r)[15]), \
          "=r"((r)[16]), "=r"((r)[17]), "=r"((r)[18]), "=r"((r)[19]), \
          "=r"((r)[20]), "=r"((r)[21]), "=r"((r)[22]), "=r"((r)[23]), \
          "=r"((r)[24]), "=r"((r)[25]), "=r"((r)[26]), "=r"((r)[27]), \
          "=r"((r)[28]), "=r"((r)[29]), "=r"((r)[30]), "=r"((r)[31]) \
        : "r"(adr))

#define TCST2(adr, r0, r1) \
    asm volatile("tcgen05.st.sync.aligned.32x32b.x2.b32 [%0], {%1, %2};" \
                 :: "r"(adr), "r"(r0), "r"(r1) : "memory")

__device__ __forceinline__ void mma_tf32(uint32_t d, uint64_t a, uint64_t b, uint32_t en) {
    asm volatile(
        "{\n\t.reg .pred p;\n\tsetp.ne.u32 p, %4, 0;\n\t"
        "tcgen05.mma.cta_group::1.kind::tf32 [%0], %1, %2, %3, {%5, %5, %5, %5}, p;\n\t}"
        :: "r"(d), "l"(a), "l"(b), "r"(IDESC), "r"(en), "r"(0u) : "memory");
}
#endif  // TC_PATH

// ================= fallback fp32 microkernel (always compiled) =================
template<int SHIFT>
__device__ __forceinline__ void gemm_tap(float C[8][8], const float* __restrict__ Wt,
                                         const float* __restrict__ B, int m0, int n0)
{
    const float* brow = B + PAD + n0 + SHIFT;
    const float* wrow = Wt + m0;
    #pragma unroll 2
    for (int k = 0; k < HID; ++k) {
        float a[8], bb[8];
        float4 a0 = *(const float4*)(wrow);
        float4 a1 = *(const float4*)(wrow + 4);
        a[0]=a0.x; a[1]=a0.y; a[2]=a0.z; a[3]=a0.w;
        a[4]=a1.x; a[5]=a1.y; a[6]=a1.z; a[7]=a1.w;
        if ((SHIFT & 3) == 0) {
            float4 b0 = *(const float4*)(brow);
            float4 b1 = *(const float4*)(brow + 4);
            bb[0]=b0.x; bb[1]=b0.y; bb[2]=b0.z; bb[3]=b0.w;
            bb[4]=b1.x; bb[5]=b1.y; bb[6]=b1.z; bb[7]=b1.w;
        } else {
            #pragma unroll
            for (int j = 0; j < 8; ++j) bb[j] = brow[j];
        }
        #pragma unroll
        for (int i = 0; i < 8; ++i)
            #pragma unroll
            for (int j = 0; j < 8; ++j)
                C[i][j] += a[i] * bb[j];
        wrow += HID;
        brow += XS;
    }
}

// ------------------------------------------------------------------
// Main kernel: tcgen05 body on sm_103a, fp32 body otherwise.
// 256 threads / CTA, one node per CTA, dynamic smem.
// ------------------------------------------------------------------
#define SMEM_TOTAL 206336   // bytes (max of both paths + 1KB align pad)

__global__ __launch_bounds__(256, 1) void k_main(
    const int* __restrict__ nidx, const int* __restrict__ nlen,
    const float* __restrict__ ssmB, const float* __restrict__ convB,
    const float* __restrict__ lnW, const float* __restrict__ lnB,
    const float* __restrict__ outW, const float* __restrict__ outB)
{
    extern __shared__ float smf[];
    const int n = blockIdx.x;
    const int tid = threadIdx.x;
    const int len = nlen[n];

#if TC_PATH
    // -------- align base to 1024B for SW128 tiles --------
    uint32_t raw = smem_u32(smf);
    uint32_t sbase = (raw + 1023u) & ~1023u;
    float* bas = smf + (sbase - raw) / 4;

    float* Bt   = bas;                    // 16384 floats (64KB)
    float* Par  = bas + 49152;            // 1280
    float* RedS = bas + 50432;            // 256
    float* RedQ = bas + 50688;            // 256
    float* Svec = bas + 50944;            // 128
    uint32_t Baddr = sbase;
    uint32_t Aaddr[2] = {sbase + 65536u, sbase + 131072u};
    uint32_t miscb = sbase + 204288u;     // tmem ptr @+0; mbars @+8..
    uint32_t mb_tma[2] = {miscb + 8, miscb + 16};
    uint32_t mb_mma[2] = {miscb + 24, miscb + 32};
    uint32_t mb_grp = miscb + 40;

    const int w = tid >> 5, lane = tid & 31;
    const int h = w >> 2;                  // column half
    const int c = (w & 3) * 32 + lane;     // channel owned in TMEM rows
    const uint32_t woff = (uint32_t)(w & 3) << 21;

    if (tid == 0) {
        MBAR_INIT(mb_tma[0], 1); MBAR_INIT(mb_tma[1], 1);
        MBAR_INIT(mb_mma[0], 1); MBAR_INIT(mb_mma[1], 1);
        MBAR_INIT(mb_grp, 1);
    }
    for (int e = tid; e < 128; e += 256) Par[e] = ssmB[e];
    for (int e = tid; e < 384; e += 256) Par[128 + e] = convB[e];
    for (int e = tid; e < 384; e += 256) Par[512 + e] = lnW[e];
    for (int e = tid; e < 384; e += 256) Par[896 + e] = lnB[e];
    if (w == 0) TC_ALLOC(miscb, 512);
    __syncthreads();
    uint32_t tmem;
    asm("ld.shared.b32 %0, [%1];" : "=r"(tmem) : "r"(miscb));
    if (w == 0) TC_RELINQ();

    if (tid == 0) {   // preload tiles 0 and 2 (consumption order)
        MBAR_EXPECT(mb_tma[0], 65536);
        bulk_g2s(Aaddr[0], g_Wswz, 65536, mb_tma[0]);
        MBAR_EXPECT(mb_tma[1], 65536);
        bulk_g2s(Aaddr[1], g_Wswz + 2 * 16384, 65536, mb_tma[1]);
    }

    // gather masked neighbor rows: B[l][k] = H[idx[l]][k]
    const int* idxrow = nidx + n * MAXL;
    for (int e = tid; e < MAXL * HID; e += 256) {
        int l = e >> 7, k = e & 127;
        float v = 0.f;
        if (l < len) v = g_H[idxrow[l] * HID + k];
        *(float*)((char*)Bt + swz_off(l, k)) = tf32r(v);
    }

    // zero the 8 side-window margin columns once
    if (h == 0) {
        uint32_t tb = tmem + woff;
        TCST2(tb + SA, 0u, 0u);        TCST2(tb + SA + 130, 0u, 0u);
        TCST2(tb + SB, 0u, 0u);        TCST2(tb + SB + 130, 0u, 0u);
        TC_WAIT_ST();
        TC_FENCE_BEFORE();
    }

    int tma_ph[2] = {0, 0}, mma_ph[2] = {0, 0};
    int cons = 0;
    uint32_t va[32], vb[32];

    for (int stage = 0; stage < 4; ++stage) {
        __syncthreads();   // B tile (and margins) ready

        if (tid == 0) {
            const int TSEQ[10] = {0, 2, 1, 3, 5, 4, 6, 8, 7, 9};
            FENCE_PROXY();
            TC_FENCE_AFTER();
            uint64_t bd = DESC_BASE | ((uint64_t)((Baddr >> 4) & 0x3FFFu));
            int ntaps = (stage == 0) ? 1 : 3;
            for (int q = 0; q < ntaps; ++q) {
                uint32_t dadr; uint32_t first_acc;
                if (stage == 0) {
                    dadr = tmem + D0; first_acc = 0u;
                } else {
                    int layer = stage - 1;
                    int kk = (q == 0) ? 1 : ((q == 1) ? 0 : 2);
                    int sft = (kk - 1) << layer;
                    if (layer == 0 && kk == 0)      { dadr = tmem + SA + 2; first_acc = 0u; }
                    else if (layer == 0 && kk == 2) { dadr = tmem + SB + 2; first_acc = 0u; }
                    else { dadr = tmem + (uint32_t)(D0 - sft); first_acc = (kk != 1) ? 1u : 0u; }
                }
                int bidx = cons & 1;
                mbar_wait(mb_tma[bidx], tma_ph[bidx]); tma_ph[bidx] ^= 1;
                uint64_t ad = DESC_BASE | ((uint64_t)((Aaddr[bidx] >> 4) & 0x3FFFu));
                #pragma unroll
                for (int ks = 0; ks < 16; ++ks) {
                    uint32_t o = (uint32_t)((ks & 3) * 2 + (ks >> 2) * 1024);
                    mma_tf32(dadr, ad + o, bd + o, (ks > 0) ? 1u : first_acc);
                }
                TC_COMMIT(mb_mma[bidx]);
                if (cons + 2 <= 9) {
                    mbar_wait(mb_mma[bidx], mma_ph[bidx]); mma_ph[bidx] ^= 1;
                    MBAR_EXPECT(mb_tma[bidx], 65536);
                    bulk_g2s(Aaddr[bidx], g_Wswz + TSEQ[cons + 2] * 16384, 65536, mb_tma[bidx]);
                }
                cons++;
            }
            TC_COMMIT(mb_grp);
        }
        mbar_wait(mb_grp, stage & 1);
        TC_FENCE_AFTER();

        // ---- read D (combine windows for layer 0) ----
        TCLD32(va, tmem + woff + (uint32_t)(D0 + 64 * h));
        TCLD32(vb, tmem + woff + (uint32_t)(D0 + 64 * h + 32));
        if (stage == 1) {
            uint32_t ta[32], tb2[32];
            TCLD32(ta,  tmem + woff + (uint32_t)(SA + 1 + 64 * h));
            TCLD32(tb2, tmem + woff + (uint32_t)(SA + 1 + 64 * h + 32));
            TC_WAIT_LD();
            #pragma unroll
            for (int j = 0; j < 32; ++j) {
                va[j] = __float_as_uint(__uint_as_float(va[j]) + __uint_as_float(ta[j]));
                vb[j] = __float_as_uint(__uint_as_float(vb[j]) + __uint_as_float(tb2[j]));
            }
            TCLD32(ta,  tmem + woff + (uint32_t)(SB + 3 + 64 * h));
            TCLD32(tb2, tmem + woff + (uint32_t)(SB + 3 + 64 * h + 32));
            TC_WAIT_LD();
            #pragma unroll
            for (int j = 0; j < 32; ++j) {
                va[j] = __float_as_uint(__uint_as_float(va[j]) + __uint_as_float(ta[j]));
                vb[j] = __float_as_uint(__uint_as_float(vb[j]) + __uint_as_float(tb2[j]));
            }
        } else {
            TC_WAIT_LD();
        }

        if (stage == 0) {
            float bv = Par[c];
            #pragma unroll
            for (int j = 0; j < 32; ++j) {
                int l = 64 * h + j;
                *(float*)((char*)Bt + swz_off(l, c)) = tf32r(__uint_as_float(va[j]) + bv);
            }
            #pragma unroll
            for (int j = 0; j < 32; ++j) {
                int l = 64 * h + 32 + j;
                *(float*)((char*)Bt + swz_off(l, c)) = tf32r(__uint_as_float(vb[j]) + bv);
            }
        } else {
            int layer = stage - 1;
            float bv = Par[128 + layer * 128 + c];
            float s = 0.f, q = 0.f;
            #pragma unroll
            for (int j = 0; j < 32; ++j) {
                float z = gelu_exact(__uint_as_float(va[j]) + bv);
                va[j] = __float_as_uint(z); s += z; q += z * z;
            }
            #pragma unroll
            for (int j = 0; j < 32; ++j) {
                float z = gelu_exact(__uint_as_float(vb[j]) + bv);
                vb[j] = __float_as_uint(z); s += z; q += z * z;
            }
            RedS[h * 128 + c] = s;
            RedQ[h * 128 + c] = q;
            __syncthreads();
            float st = s + RedS[(h ^ 1) * 128 + c];
            float qt = q + RedQ[(h ^ 1) * 128 + c];
            float m   = st * (1.f / 128.f);
            float inv = rsqrtf(qt * (1.f / 128.f) - m * m + EPS);
            const float* lw = Par + 512 + layer * 128;
            const float* lb = Par + 896 + layer * 128;
            if (stage < 3) {
                #pragma unroll
                for (int j = 0; j < 32; ++j) {
                    int l = 64 * h + j;
                    float o = (__uint_as_float(va[j]) - m) * inv * lw[l] + lb[l];
                    *(float*)((char*)Bt + swz_off(l, c)) = tf32r(o);
                }
                #pragma unroll
                for (int j = 0; j < 32; ++j) {
                    int l = 64 * h + 32 + j;
                    float o = (__uint_as_float(vb[j]) - m) * inv * lw[l] + lb[l];
                    *(float*)((char*)Bt + swz_off(l, c)) = tf32r(o);
                }
            } else {
                float ms = 0.f;
                #pragma unroll
                for (int j = 0; j < 32; ++j) {
                    int l = 64 * h + j;
                    float o = (__uint_as_float(va[j]) - m) * inv * lw[l] + lb[l];
                    if (l < len) ms += o;
                }
                #pragma unroll
                for (int j = 0; j < 32; ++j) {
                    int l = 64 * h + 32 + j;
                    float o = (__uint_as_float(vb[j]) - m) * inv * lw[l] + lb[l];
                    if (l < len) ms += o;
                }
                __syncthreads();
                RedS[h * 128 + c] = ms;
                __syncthreads();
                if (h == 0) Svec[c] = RedS[c] + RedS[128 + c];
                __syncthreads();
                if (tid < 128) {
                    float acc = 0.f;
                    #pragma unroll 8
                    for (int cc = 0; cc < 128; ++cc)
                        acc += Svec[cc] * outW[cc * 128 + tid];
                    float cnt = (float)len, denom = fmaxf(cnt, 1.f);
                    g_pooled[n * 128 + tid] = (acc + cnt * outB[tid]) / denom;
                }
            }
        }
    }
    __syncthreads();
    if (w == 0) TC_DEALLOC(tmem, 512);

#else  // ===================== fp32 fallback body =====================
    float* Xa   = smf;
    float* Xb   = smf + HID * XS;
    float* Wt   = smf + 2 * HID * XS;
    float* svec = Wt + HID * HID;

    const int tx = tid & 15, ty = tid >> 4;
    const int m0 = ty * 8, n0 = tx * 8;

    for (int e = tid; e < HID * 8; e += 256) {
        int r = e >> 3, p = e & 7;
        int col = (p < PAD) ? p : (XS - 8 + p);
        Xa[r * XS + col] = 0.f;
        Xb[r * XS + col] = 0.f;
    }
    const int* idxrow = nidx + n * MAXL;
    for (int e = tid; e < MAXL * HID; e += 256) {
        int l = e >> 7, k = e & (HID - 1);
        float v = 0.f;
        if (l < len) v = g_H[idxrow[l] * HID + k];
        Xa[k * XS + PAD + l] = v;
    }
    for (int e = tid; e < HID * HID; e += 256) Wt[e] = g_Wplain[e];
    __syncthreads();

    float C[8][8];
    #pragma unroll
    for (int i = 0; i < 8; ++i)
        #pragma unroll
        for (int j = 0; j < 8; ++j) C[i][j] = 0.f;

    gemm_tap<0>(C, Wt, Xa, m0, n0);

    #pragma unroll
    for (int i = 0; i < 8; ++i) {
        float bv = ssmB[m0 + i];
        #pragma unroll
        for (int j = 0; j < 8; ++j)
            Xb[(m0 + i) * XS + PAD + n0 + j] = C[i][j] + bv;
    }
    __syncthreads();

    float* src = Xb;
    float* dst = Xa;

    for (int layer = 0; layer < 3; ++layer) {
        const int d = 1 << layer;
        #pragma unroll
        for (int i = 0; i < 8; ++i)
            #pragma unroll
            for (int j = 0; j < 8; ++j) C[i][j] = 0.f;

        for (int kk = 0; kk < 3; ++kk) {
            const float* wsrc = g_Wplain + (1 + layer * 3 + kk) * (HID * HID);
            for (int e = tid; e < HID * HID; e += 256) Wt[e] = wsrc[e];
            __syncthreads();
            int shift = (kk - 1) * d;
            switch (shift) {
                case -4: gemm_tap<-4>(C, Wt, src, m0, n0); break;
                case -2: gemm_tap<-2>(C, Wt, src, m0, n0); break;
                case -1: gemm_tap<-1>(C, Wt, src, m0, n0); break;
                case  0: gemm_tap< 0>(C, Wt, src, m0, n0); break;
                case  1: gemm_tap< 1>(C, Wt, src, m0, n0); break;
                case  2: gemm_tap< 2>(C, Wt, src, m0, n0); break;
                default: gemm_tap< 4>(C, Wt, src, m0, n0); break;
            }
            __syncthreads();
        }

        float rs[8], rq[8];
        #pragma unroll
        for (int i = 0; i < 8; ++i) {
            float bv = convB[layer * HID + m0 + i];
            rs[i] = 0.f; rq[i] = 0.f;
            #pragma unroll
            for (int j = 0; j < 8; ++j) {
                float z = gelu_exact(C[i][j] + bv);
                C[i][j] = z;
                rs[i] += z;
                rq[i] += z * z;
            }
        }
        #pragma unroll
        for (int i = 0; i < 8; ++i) {
            #pragma unroll
            for (int off = 8; off; off >>= 1) {
                rs[i] += __shfl_xor_sync(0xffffffffu, rs[i], off);
                rq[i] += __shfl_xor_sync(0xffffffffu, rq[i], off);
            }
        }

        float lw[8], lb[8];
        #pragma unroll
        for (int j = 0; j < 8; ++j) {
            lw[j] = lnW[layer * HID + n0 + j];
            lb[j] = lnB[layer * HID + n0 + j];
        }

        if (layer < 2) {
            #pragma unroll
            for (int i = 0; i < 8; ++i) {
                float m   = rs[i] * (1.f / MAXL);
                float inv = rsqrtf(rq[i] * (1.f / MAXL) - m * m + EPS);
                #pragma unroll
                for (int j = 0; j < 8; ++j)
                    dst[(m0 + i) * XS + PAD + n0 + j] = (C[i][j] - m) * inv * lw[j] + lb[j];
            }
            float* t = src; src = dst; dst = t;
            __syncthreads();
        } else {
            float ms[8];
            #pragma unroll
            for (int i = 0; i < 8; ++i) {
                float m   = rs[i] * (1.f / MAXL);
                float inv = rsqrtf(rq[i] * (1.f / MAXL) - m * m + EPS);
                ms[i] = 0.f;
                #pragma unroll
                for (int j = 0; j < 8; ++j) {
                    float o = (C[i][j] - m) * inv * lw[j] + lb[j];
                    if (n0 + j < len) ms[i] += o;
                }
            }
            #pragma unroll
            for (int i = 0; i < 8; ++i) {
                #pragma unroll
                for (int off = 8; off; off >>= 1)
                    ms[i] += __shfl_xor_sync(0xffffffffu, ms[i], off);
            }
            if (tx == 0) {
                #pragma unroll
                for (int i = 0; i < 8; ++i) svec[m0 + i] = ms[i];
            }
        }
    }
    __syncthreads();

    if (tid < HID) {
        float acc = 0.f;
        #pragma unroll 8
        for (int cc = 0; cc < HID; ++cc)
            acc += svec[cc] * outW[cc * HID + tid];
        float cnt   = (float)len;
        float denom = fmaxf(cnt, 1.f);
        g_pooled[n * HID + tid] = (acc + cnt * outB[tid]) / denom;
    }
#endif
}

// ------------------------------------------------------------------
// Classifier head
// ------------------------------------------------------------------
__global__ __launch_bounds__(64) void k_cls(
    const float* __restrict__ W1, const float* __restrict__ b1,
    const float* __restrict__ W2, const float* __restrict__ b2,
    float* __restrict__ out)
{
    __shared__ float p[HID];
    __shared__ float g[64];
    int n = blockIdx.x;
    int j = threadIdx.x;
    p[j]      = g_pooled[n * HID + j];
    p[j + 64] = g_pooled[n * HID + j + 64];
    __syncthreads();
    float acc = b1[j];
    #pragma unroll 8
    for (int cc = 0; cc < HID; ++cc)
        acc += p[cc] * W1[cc * 64 + j];
    g[j] = gelu_exact(acc);
    __syncthreads();
    float acc2 = b2[j];
    #pragma unroll 8
    for (int t = 0; t < 64; ++t)
        acc2 += g[t] * W2[t * 64 + j];
    out[n * NCLS + j] = acc2;
}

// ------------------------------------------------------------------
extern "C" void kernel_launch(void* const* d_in, const int* in_sizes, int n_in,
                              void* d_out, int out_size)
{
    (void)in_sizes; (void)n_in; (void)out_size;
    const float* node_feat  = (const float*)d_in[0];
    const int*   nidx       = (const int*)  d_in[1];
    const int*   nlen       = (const int*)  d_in[2];
    const float* local_W    = (const float*)d_in[3];
    const float* local_b    = (const float*)d_in[4];
    const float* local_ln_w = (const float*)d_in[5];
    const float* local_ln_b = (const float*)d_in[6];
    const float* ssm_in_W   = (const float*)d_in[7];
    const float* ssm_in_b   = (const float*)d_in[8];
    const float* conv_w     = (const float*)d_in[9];
    const float* conv_b     = (const float*)d_in[10];
    const float* ln_w       = (const float*)d_in[11];
    const float* ln_b       = (const float*)d_in[12];
    const float* out_W      = (const float*)d_in[13];
    const float* out_b      = (const float*)d_in[14];
    const float* cls_W1     = (const float*)d_in[15];
    const float* cls_b1     = (const float*)d_in[16];
    const float* cls_W2     = (const float*)d_in[17];
    const float* cls_b2     = (const float*)d_in[18];
    float* out = (float*)d_out;

    cudaFuncSetAttribute(k_main, cudaFuncAttributeMaxDynamicSharedMemorySize, SMEM_TOTAL);

    k_prep<<<(10 * HID * HID + 255) / 256, 256>>>(ssm_in_W, conv_w);
    k_local8<<<N_NODES / 8, 128>>>(node_feat, local_W, local_b, local_ln_w, local_ln_b);
    k_main<<<N_NODES, 256, SMEM_TOTAL>>>(nidx, nlen, ssm_in_b, conv_b, ln_w, ln_b, out_W, out_b);
    k_cls<<<N_NODES, 64>>>(cls_W1, cls_b1, cls_W2, cls_b2, out);
}